// round 6
// baseline (speedup 1.0000x reference)
#include <cuda_runtime.h>
#include <cuda_fp16.h>

// FakeReviewGNN: 2-layer GCN, N=100000, 7 -> 64 -> 32 -> 2.
// Per-call CSR (counting sort by dst) -> atomic-free gather aggregation.
//   k_count        : histogram of dst (8 edges/thread, cnt pre-zeroed by k_final)
//   k_scan_partial : per-block sums of cnt
//   k_scan_apply   : exclusive scan + rowptr/wcur + fused prep (dinv, xd=x*dinv)
//   k_fill         : counting-sort edges into col[] (8 edges/thread ILP)
//   k_transform    : gather7 + (p@W1 -> relu -> @W2)*dinv -> g2 (fp16 store)
//   k_final        : half2 gather32 + relu + classifier + log_softmax + cnt reset

#define MAXN 100000
#define MAXE 1600000
#define F1 64
#define F2 32

#define SCAN_T 256
#define SCAN_C 4
#define SCAN_CHUNK (SCAN_T * SCAN_C)   // 1024

__device__ int   d_cnt   [MAXN];        // zero-init; k_final resets after use
__device__ int   d_rowptr[MAXN + 1];
__device__ int   d_wcur  [MAXN];
__device__ int   d_bsum  [256];
__device__ int   d_col   [MAXE];
__device__ float d_dinv  [MAXN];
__device__ __align__(128) float  d_xd [MAXN * 8];
__device__ __align__(128) __half d_g2h[MAXN * F2];   // fp16 layer-2 features

// ---- histogram (cnt assumed zero on entry), 8 edges / thread ---------------

__global__ void k_count_v4(const int4* __restrict__ dst4, int E4) {
    int i = (blockIdx.x * blockDim.x + threadIdx.x) * 2;
    if (i >= E4) return;
    int4 a = dst4[i];
    atomicAdd(&d_cnt[a.x], 1);
    atomicAdd(&d_cnt[a.y], 1);
    atomicAdd(&d_cnt[a.z], 1);
    atomicAdd(&d_cnt[a.w], 1);
    if (i + 1 < E4) {
        int4 b = dst4[i + 1];
        atomicAdd(&d_cnt[b.x], 1);
        atomicAdd(&d_cnt[b.y], 1);
        atomicAdd(&d_cnt[b.z], 1);
        atomicAdd(&d_cnt[b.w], 1);
    }
}

__global__ void k_count_sc(const int* __restrict__ dst, int E) {
    int i = blockIdx.x * blockDim.x + threadIdx.x;
    if (i < E) atomicAdd(&d_cnt[dst[i]], 1);
}

// ---- scan phase 1: per-block partial sums ----------------------------------

__global__ void k_scan_partial(int n) {
    __shared__ int sh[SCAN_T];
    int base = blockIdx.x * SCAN_CHUNK + threadIdx.x * SCAN_C;
    int s = 0;
    #pragma unroll
    for (int j = 0; j < SCAN_C; j++) {
        int idx = base + j;
        if (idx < n) s += d_cnt[idx];
    }
    sh[threadIdx.x] = s;
    __syncthreads();
    for (int off = SCAN_T / 2; off > 0; off >>= 1) {
        if (threadIdx.x < off) sh[threadIdx.x] += sh[threadIdx.x + off];
        __syncthreads();
    }
    if (threadIdx.x == 0) d_bsum[blockIdx.x] = sh[0];
}

// ---- scan phase 2: apply + fused prep --------------------------------------

__global__ void k_scan_apply(const float* __restrict__ x, int n, int E) {
    __shared__ int sh[SCAN_T];
    __shared__ int s_boff;
    int tid = threadIdx.x;

    {   // redundant top-scan: offset = sum of bsum[j], j < blockIdx.x
        int v = (tid < blockIdx.x) ? d_bsum[tid] : 0;
        sh[tid] = v;
        __syncthreads();
        for (int off = SCAN_T / 2; off > 0; off >>= 1) {
            if (tid < off) sh[tid] += sh[tid + off];
            __syncthreads();
        }
        if (tid == 0) s_boff = sh[0];
        __syncthreads();
    }

    int base = blockIdx.x * SCAN_CHUNK + tid * SCAN_C;
    int loc[SCAN_C];
    int s = 0;
    #pragma unroll
    for (int j = 0; j < SCAN_C; j++) {
        int idx = base + j;
        loc[j] = (idx < n) ? d_cnt[idx] : 0;
        s += loc[j];
    }
    sh[tid] = s;
    __syncthreads();
    for (int off = 1; off < SCAN_T; off <<= 1) {
        int t = (tid >= off) ? sh[tid - off] : 0;
        __syncthreads();
        sh[tid] += t;
        __syncthreads();
    }
    int run = s_boff + sh[tid] - s;

    #pragma unroll
    for (int j = 0; j < SCAN_C; j++) {
        int idx = base + j;
        if (idx < n) {
            d_rowptr[idx] = run;
            d_wcur[idx]   = run;
            run += loc[j];
            float dv = rsqrtf((float)(loc[j] + 1));   // +1 self loop
            d_dinv[idx] = dv;
            const float* xi = x + (long long)idx * 7;
            float4 a, b;
            a.x = xi[0] * dv; a.y = xi[1] * dv; a.z = xi[2] * dv; a.w = xi[3] * dv;
            b.x = xi[4] * dv; b.y = xi[5] * dv; b.z = xi[6] * dv; b.w = 0.0f;
            reinterpret_cast<float4*>(d_xd)[idx * 2]     = a;
            reinterpret_cast<float4*>(d_xd)[idx * 2 + 1] = b;
        }
    }
    if (blockIdx.x == 0 && tid == 0) d_rowptr[n] = E;
}

// ---- CSR fill, 8 edges / thread (8 independent atomic chains) --------------

__global__ void k_fill_v4(const int4* __restrict__ src4,
                          const int4* __restrict__ dst4, int E4) {
    int i = (blockIdx.x * blockDim.x + threadIdx.x) * 2;
    if (i >= E4) return;
    int4 s0 = src4[i];
    int4 v0 = dst4[i];
    bool two = (i + 1 < E4);
    int4 s1, v1;
    if (two) { s1 = src4[i + 1]; v1 = dst4[i + 1]; }

    int p0 = atomicAdd(&d_wcur[v0.x], 1);
    int p1 = atomicAdd(&d_wcur[v0.y], 1);
    int p2 = atomicAdd(&d_wcur[v0.z], 1);
    int p3 = atomicAdd(&d_wcur[v0.w], 1);
    int p4 = 0, p5 = 0, p6 = 0, p7 = 0;
    if (two) {
        p4 = atomicAdd(&d_wcur[v1.x], 1);
        p5 = atomicAdd(&d_wcur[v1.y], 1);
        p6 = atomicAdd(&d_wcur[v1.z], 1);
        p7 = atomicAdd(&d_wcur[v1.w], 1);
    }
    d_col[p0] = s0.x;
    d_col[p1] = s0.y;
    d_col[p2] = s0.z;
    d_col[p3] = s0.w;
    if (two) {
        d_col[p4] = s1.x;
        d_col[p5] = s1.y;
        d_col[p6] = s1.z;
        d_col[p7] = s1.w;
    }
}

__global__ void k_fill_sc(const int* __restrict__ src,
                          const int* __restrict__ dst, int E) {
    int e = blockIdx.x * blockDim.x + threadIdx.x;
    if (e >= E) return;
    d_col[atomicAdd(&d_wcur[dst[e]], 1)] = src[e];
}

// ---- fused gather7 + dense transform: one warp per node --------------------

__global__ void k_transform(const float* __restrict__ W1,
                            const float* __restrict__ b1,
                            const float* __restrict__ W2, int n) {
    __shared__ float W1s[7 * F1];
    __shared__ float b1s[F1];
    __shared__ float W2s[F1 * F2];
    __shared__ float hs[8][F1];

    for (int i = threadIdx.x; i < 7 * F1;  i += blockDim.x) W1s[i] = W1[i];
    for (int i = threadIdx.x; i < F1;      i += blockDim.x) b1s[i] = b1[i];
    for (int i = threadIdx.x; i < F1 * F2; i += blockDim.x) W2s[i] = W2[i];
    __syncthreads();

    int warp = threadIdx.x >> 5;
    int lane = threadIdx.x & 31;
    int node = blockIdx.x * 8 + warp;
    if (node >= n) return;

    int beg = d_rowptr[node], end = d_rowptr[node + 1];
    int sub = lane >> 3;       // neighbor slot 0..3
    int f   = lane & 7;        // feature 0..7

    float acc = 0.0f;
    int i = beg + sub;
    for (; i + 4 < end; i += 8) {   // 8 gathers/warp-iter in flight
        int c0 = d_col[i];
        int c1 = d_col[i + 4];
        float v0 = __ldg(&d_xd[(long long)c0 * 8 + f]);
        float v1 = __ldg(&d_xd[(long long)c1 * 8 + f]);
        acc += v0 + v1;
    }
    if (i < end)
        acc += __ldg(&d_xd[(long long)d_col[i] * 8 + f]);

    acc += __shfl_down_sync(0xffffffffu, acc, 16);
    acc += __shfl_down_sync(0xffffffffu, acc, 8);

    float pv = 0.0f;
    if (lane < 8) pv = acc + d_xd[(long long)node * 8 + lane];  // self loop

    float dv = d_dinv[node];
    float a0 = 0.0f, a1 = 0.0f;
    #pragma unroll
    for (int k = 0; k < 7; k++) {
        float pk = __shfl_sync(0xffffffffu, pv, k);
        a0 += pk * W1s[k * F1 + lane];
        a1 += pk * W1s[k * F1 + 32 + lane];
    }
    hs[warp][lane]      = fmaxf(dv * a0 + b1s[lane],      0.0f);
    hs[warp][lane + 32] = fmaxf(dv * a1 + b1s[lane + 32], 0.0f);
    __syncwarp();

    float a = 0.0f;
    #pragma unroll
    for (int k = 0; k < F1; k++)
        a += hs[warp][k] * W2s[k * F2 + lane];

    d_g2h[(node << 5) + lane] = __float2half(a * dv);   // fp16 payload
}

// ---- fused half2 gather32 + classifier + log_softmax + cnt reset -----------
// warp per node: lanes 0-15 neighbors (even slots), 16-31 (odd slots);
// lane covers feature pair {2*fp, 2*fp+1} as one half2 (64B/neighbor).

__global__ void k_final(const float* __restrict__ b2,
                        const float* __restrict__ Wc,
                        const float* __restrict__ bc,
                        float* __restrict__ out, int n) {
    int warp = threadIdx.x >> 5;
    int lane = threadIdx.x & 31;
    int node = blockIdx.x * 8 + warp;
    if (node >= n) return;

    int sub = lane >> 4;        // 0 or 1
    int fp  = lane & 15;        // feature-pair 0..15
    const __half2* g2 = reinterpret_cast<const __half2*>(d_g2h);

    float ax = 0.0f, ay = 0.0f;
    if (sub == 0) {             // self loop counted once
        float2 sv = __half22float2(g2[(node << 4) + fp]);
        ax = sv.x; ay = sv.y;
    }

    int beg = d_rowptr[node], end = d_rowptr[node + 1];
    int i = beg + sub;
    for (; i + 6 < end; i += 8) {       // 4 neighbors per sub in flight
        int c0 = d_col[i];
        int c1 = d_col[i + 2];
        int c2 = d_col[i + 4];
        int c3 = d_col[i + 6];
        float2 v0 = __half22float2(__ldg(&g2[(c0 << 4) + fp]));
        float2 v1 = __half22float2(__ldg(&g2[(c1 << 4) + fp]));
        float2 v2 = __half22float2(__ldg(&g2[(c2 << 4) + fp]));
        float2 v3 = __half22float2(__ldg(&g2[(c3 << 4) + fp]));
        ax += (v0.x + v1.x) + (v2.x + v3.x);
        ay += (v0.y + v1.y) + (v2.y + v3.y);
    }
    for (; i < end; i += 2) {
        float2 v = __half22float2(__ldg(&g2[(d_col[i] << 4) + fp]));
        ax += v.x; ay += v.y;
    }

    // merge the two neighbor halves (same features, different neighbor subsets)
    ax += __shfl_down_sync(0xffffffffu, ax, 16);
    ay += __shfl_down_sync(0xffffffffu, ay, 16);

    float dv = d_dinv[node];
    float h0 = fmaxf(dv * ax + b2[2 * fp],     0.0f);
    float h1 = fmaxf(dv * ay + b2[2 * fp + 1], 0.0f);
    float l0 = h0 * Wc[4 * fp]     + h1 * Wc[4 * fp + 2];
    float l1 = h0 * Wc[4 * fp + 1] + h1 * Wc[4 * fp + 3];
    #pragma unroll
    for (int off = 8; off > 0; off >>= 1) {
        l0 += __shfl_down_sync(0xffffffffu, l0, off);
        l1 += __shfl_down_sync(0xffffffffu, l1, off);
    }
    if (lane == 0) {
        l0 += bc[0];
        l1 += bc[1];
        float m   = fmaxf(l0, l1);
        float lse = m + logf(expf(l0 - m) + expf(l1 - m));
        out[(long long)node * 2]     = l0 - lse;
        out[(long long)node * 2 + 1] = l1 - lse;
        d_cnt[node] = 0;   // reset histogram for next replay (deterministic)
    }
}

// ---- launch ----------------------------------------------------------------

extern "C" void kernel_launch(void* const* d_in, const int* in_sizes, int n_in,
                              void* d_out, int out_size) {
    const float* x  = (const float*)d_in[0];
    const int*   ei = (const int*)  d_in[1];
    const float* W1 = (const float*)d_in[2];
    const float* b1 = (const float*)d_in[3];
    const float* W2 = (const float*)d_in[4];
    const float* b2 = (const float*)d_in[5];
    const float* Wc = (const float*)d_in[6];
    const float* bc = (const float*)d_in[7];
    float* out = (float*)d_out;

    int n = in_sizes[0] / 7;     // 100000
    int E = in_sizes[1] / 2;     // 1600000
    const int* src = ei;
    const int* dst = ei + E;

    const int T = 256;
    int nblk = (n + SCAN_CHUNK - 1) / SCAN_CHUNK;   // 98

    bool vec_ok = (E % 4 == 0) && ((((unsigned long long)src) & 15ull) == 0)
                                && ((((unsigned long long)dst) & 15ull) == 0);

    if (vec_ok) {
        int E4 = E / 4;
        int thr = (E4 + 1) / 2;                      // 2 int4 per thread
        k_count_v4<<<(thr + T - 1) / T, T>>>((const int4*)dst, E4);
    } else {
        k_count_sc<<<(E + T - 1) / T, T>>>(dst, E);
    }

    k_scan_partial<<<nblk, SCAN_T>>>(n);
    k_scan_apply  <<<nblk, SCAN_T>>>(x, n, E);

    if (vec_ok) {
        int E4 = E / 4;
        int thr = (E4 + 1) / 2;
        k_fill_v4<<<(thr + T - 1) / T, T>>>((const int4*)src, (const int4*)dst, E4);
    } else {
        k_fill_sc<<<(E + T - 1) / T, T>>>(src, dst, E);
    }

    k_transform<<<(n + 7) / 8, T>>>(W1, b1, W2, n);
    k_final    <<<(n + 7) / 8, T>>>(b2, Wc, bc, out, n);
}

// round 7
// speedup vs baseline: 1.1895x; 1.1895x over previous
#include <cuda_runtime.h>
#include <cuda_fp16.h>

// FakeReviewGNN: 2-layer GCN, N=100000, 7 -> 64 -> 32 -> 2.
// CSR-free scatter pipeline (atomic payloads minimized):
//   k_count     : dst histogram (cnt pre-zeroed / reset by k_final)
//   k_prep      : dinv = rsqrt(cnt+1); xd = x*dinv (pad 7->8); p init = xd
//   k_scatter8  : p[dst] += xd[src]           (2 x red.v4.f32 / edge)
//   k_transform : h1 = relu(dinv*(p@W1)+b1); g2 = (h1@W2)*dinv -> fp16
//                 g2h[node] and s2h[node] (self-loop init)
//   k_scatter32h: s2h[dst] += g2h[src]        (4 x red.v4.f16x2 / edge)
//   k_final     : h2 = relu(dinv*s2+b2); log_softmax(h2@Wc+bc); reset cnt

#define MAXN 100000
#define F1 64
#define F2 32

__device__ int   d_cnt [MAXN];          // zero-init; k_final resets after use
__device__ float d_dinv[MAXN];
__device__ __align__(128) float  d_xd [MAXN * 8];
__device__ __align__(128) float  d_p  [MAXN * 8];
__device__ __align__(128) __half d_g2h[MAXN * F2];
__device__ __align__(128) __half d_s2h[MAXN * F2];

__device__ __forceinline__ void red_add_v4f(float4* addr, float4 v) {
    asm volatile("red.global.add.v4.f32 [%0], {%1, %2, %3, %4};"
                 :: "l"(addr), "f"(v.x), "f"(v.y), "f"(v.z), "f"(v.w)
                 : "memory");
}

__device__ __forceinline__ void red_add_v4h2(uint4* addr, uint4 v) {
    asm volatile("red.global.add.noftz.v4.f16x2 [%0], {%1, %2, %3, %4};"
                 :: "l"(addr), "r"(v.x), "r"(v.y), "r"(v.z), "r"(v.w)
                 : "memory");
}

// ---- histogram (cnt assumed zero on entry) ---------------------------------

__global__ void k_count_v4(const int4* __restrict__ dst4, int E4) {
    int i = blockIdx.x * blockDim.x + threadIdx.x;
    if (i >= E4) return;
    int4 d = dst4[i];
    atomicAdd(&d_cnt[d.x], 1);
    atomicAdd(&d_cnt[d.y], 1);
    atomicAdd(&d_cnt[d.z], 1);
    atomicAdd(&d_cnt[d.w], 1);
}

__global__ void k_count_sc(const int* __restrict__ dst, int E) {
    int i = blockIdx.x * blockDim.x + threadIdx.x;
    if (i < E) atomicAdd(&d_cnt[dst[i]], 1);
}

// ---- prep: dinv, xd = x*dinv (pad 7->8), p init = xd -----------------------

__global__ void k_prep(const float* __restrict__ x, int n) {
    int i = blockIdx.x * blockDim.x + threadIdx.x;
    if (i >= n) return;
    float dv = rsqrtf((float)(d_cnt[i] + 1));   // +1 self loop
    d_dinv[i] = dv;
    const float* xi = x + (long long)i * 7;
    float4 a, b;
    a.x = xi[0] * dv; a.y = xi[1] * dv; a.z = xi[2] * dv; a.w = xi[3] * dv;
    b.x = xi[4] * dv; b.y = xi[5] * dv; b.z = xi[6] * dv; b.w = 0.0f;
    reinterpret_cast<float4*>(d_xd)[i * 2]     = a;
    reinterpret_cast<float4*>(d_xd)[i * 2 + 1] = b;
    reinterpret_cast<float4*>(d_p )[i * 2]     = a;
    reinterpret_cast<float4*>(d_p )[i * 2 + 1] = b;
}

// ---- layer-1 scatter: p[dst] += xd[src], fp32 (2 red.v4 / edge) ------------

__global__ void k_scatter8(const int* __restrict__ src,
                           const int* __restrict__ dst, int E) {
    long long idx = (long long)blockIdx.x * blockDim.x + threadIdx.x;
    int e = (int)(idx >> 1);
    int c = (int)(idx & 1);
    if (e >= E) return;
    int u = src[e], v = dst[e];
    float4 val = reinterpret_cast<const float4*>(d_xd)[(long long)u * 2 + c];
    red_add_v4f(&reinterpret_cast<float4*>(d_p)[(long long)v * 2 + c], val);
}

// ---- fused dense transform: one warp per node ------------------------------

__global__ void k_transform(const float* __restrict__ W1,
                            const float* __restrict__ b1,
                            const float* __restrict__ W2, int n) {
    __shared__ float W1s[7 * F1];
    __shared__ float b1s[F1];
    __shared__ float W2s[F1 * F2];
    __shared__ float hs[8][F1];

    for (int i = threadIdx.x; i < 7 * F1;  i += blockDim.x) W1s[i] = W1[i];
    for (int i = threadIdx.x; i < F1;      i += blockDim.x) b1s[i] = b1[i];
    for (int i = threadIdx.x; i < F1 * F2; i += blockDim.x) W2s[i] = W2[i];
    __syncthreads();

    int warp = threadIdx.x >> 5;
    int lane = threadIdx.x & 31;
    int node = blockIdx.x * 8 + warp;
    if (node >= n) return;

    float pv = (lane < 8) ? d_p[node * 8 + lane] : 0.0f;
    float dv = d_dinv[node];

    float a0 = 0.0f, a1 = 0.0f;
    #pragma unroll
    for (int k = 0; k < 7; k++) {
        float pk = __shfl_sync(0xffffffffu, pv, k);
        a0 += pk * W1s[k * F1 + lane];
        a1 += pk * W1s[k * F1 + 32 + lane];
    }
    hs[warp][lane]      = fmaxf(dv * a0 + b1s[lane],      0.0f);
    hs[warp][lane + 32] = fmaxf(dv * a1 + b1s[lane + 32], 0.0f);
    __syncwarp();

    float a = 0.0f;
    #pragma unroll
    for (int k = 0; k < F1; k++)
        a += hs[warp][k] * W2s[k * F2 + lane];

    __half g = __float2half(a * dv);
    d_g2h[(node << 5) + lane] = g;
    d_s2h[(node << 5) + lane] = g;   // self-loop init
}

// ---- layer-2 scatter: s2h[dst] += g2h[src], fp16 (4 red.v4.f16x2 / edge) ---

__global__ void k_scatter32h(const int* __restrict__ src,
                             const int* __restrict__ dst, int E) {
    long long idx = (long long)blockIdx.x * blockDim.x + threadIdx.x;
    int e = (int)(idx >> 2);
    int c = (int)(idx & 3);
    if (e >= E) return;
    int u = src[e], v = dst[e];
    uint4 val = reinterpret_cast<const uint4*>(d_g2h)[(long long)u * 4 + c];
    red_add_v4h2(&reinterpret_cast<uint4*>(d_s2h)[(long long)v * 4 + c], val);
}

// ---- final: relu + classifier + log_softmax + cnt reset (thread/node) ------

__global__ void k_final(const float* __restrict__ b2,
                        const float* __restrict__ Wc,
                        const float* __restrict__ bc,
                        float* __restrict__ out, int n) {
    int node = blockIdx.x * blockDim.x + threadIdx.x;
    if (node >= n) return;

    float dv = d_dinv[node];
    const uint4* s4 = reinterpret_cast<const uint4*>(d_s2h) + (long long)node * 4;
    float l0 = bc[0], l1 = bc[1];

    #pragma unroll
    for (int j = 0; j < 4; j++) {
        uint4 q = s4[j];
        unsigned w[4] = {q.x, q.y, q.z, q.w};
        #pragma unroll
        for (int t = 0; t < 4; t++) {
            float2 v = __half22float2(*reinterpret_cast<const __half2*>(&w[t]));
            int k = j * 8 + t * 2;
            float h0 = fmaxf(dv * v.x + b2[k],     0.0f);
            float h1 = fmaxf(dv * v.y + b2[k + 1], 0.0f);
            l0 += h0 * Wc[k * 2]     + h1 * Wc[k * 2 + 2];
            l1 += h0 * Wc[k * 2 + 1] + h1 * Wc[k * 2 + 3];
        }
    }

    float m   = fmaxf(l0, l1);
    float lse = m + logf(expf(l0 - m) + expf(l1 - m));
    out[(long long)node * 2]     = l0 - lse;
    out[(long long)node * 2 + 1] = l1 - lse;
    d_cnt[node] = 0;   // reset histogram for next replay (deterministic)
}

// ---- launch ----------------------------------------------------------------

extern "C" void kernel_launch(void* const* d_in, const int* in_sizes, int n_in,
                              void* d_out, int out_size) {
    const float* x  = (const float*)d_in[0];
    const int*   ei = (const int*)  d_in[1];
    const float* W1 = (const float*)d_in[2];
    const float* b1 = (const float*)d_in[3];
    const float* W2 = (const float*)d_in[4];
    const float* b2 = (const float*)d_in[5];
    const float* Wc = (const float*)d_in[6];
    const float* bc = (const float*)d_in[7];
    float* out = (float*)d_out;

    int n = in_sizes[0] / 7;     // 100000
    int E = in_sizes[1] / 2;     // 1600000
    const int* src = ei;
    const int* dst = ei + E;

    const int T = 256;

    bool vec_ok = (E % 4 == 0) && ((((unsigned long long)dst) & 15ull) == 0);
    if (vec_ok) {
        int E4 = E / 4;
        k_count_v4<<<(E4 + T - 1) / T, T>>>((const int4*)dst, E4);
    } else {
        k_count_sc<<<(E + T - 1) / T, T>>>(dst, E);
    }

    k_prep<<<(n + T - 1) / T, T>>>(x, n);

    long long w1 = (long long)E * 2;
    k_scatter8<<<(unsigned)((w1 + T - 1) / T), T>>>(src, dst, E);

    k_transform<<<(n + 7) / 8, T>>>(W1, b1, W2, n);

    long long w2 = (long long)E * 4;
    k_scatter32h<<<(unsigned)((w2 + T - 1) / T), T>>>(src, dst, E);

    k_final<<<(n + T - 1) / T, T>>>(b2, Wc, bc, out, n);
}

// round 8
// speedup vs baseline: 1.5457x; 1.2995x over previous
#include <cuda_runtime.h>
#include <cuda_fp16.h>

// FakeReviewGNN: 2-layer GCN, N=100000, 7 -> 64 -> 32 -> 2.
// CSR-free scatter pipeline (atomic payloads minimized):
//   k_count     : dst histogram (cnt pre-zeroed / reset by k_final)
//   k_prep      : dinv = rsqrt(cnt+1); xd = x*dinv (pad 7->8); p init = xd
//   k_scatter8  : p[dst] += xd[src]           (2 x red.v4.f32 / edge)
//   k_transform : 4 nodes/warp, LDS-amortized GEMV chain -> g2 fp16
//   k_scatter32h: s2h[dst] += g2h[src]        (4 x red.v4.f16x2 / edge)
//   k_final     : h2 = relu(dinv*s2+b2); log_softmax(h2@Wc+bc); reset cnt

#define MAXN 100000
#define F1 64
#define F2 32

__device__ int   d_cnt [MAXN];          // zero-init; k_final resets after use
__device__ float d_dinv[MAXN];
__device__ __align__(128) float  d_xd [MAXN * 8];
__device__ __align__(128) float  d_p  [MAXN * 8];
__device__ __align__(128) __half d_g2h[MAXN * F2];
__device__ __align__(128) __half d_s2h[MAXN * F2];

__device__ __forceinline__ void red_add_v4f(float4* addr, float4 v) {
    asm volatile("red.global.add.v4.f32 [%0], {%1, %2, %3, %4};"
                 :: "l"(addr), "f"(v.x), "f"(v.y), "f"(v.z), "f"(v.w)
                 : "memory");
}

__device__ __forceinline__ void red_add_v4h2(uint4* addr, uint4 v) {
    asm volatile("red.global.add.noftz.v4.f16x2 [%0], {%1, %2, %3, %4};"
                 :: "l"(addr), "r"(v.x), "r"(v.y), "r"(v.z), "r"(v.w)
                 : "memory");
}

// ---- histogram (cnt assumed zero on entry) ---------------------------------

__global__ void k_count_v4(const int4* __restrict__ dst4, int E4) {
    int i = blockIdx.x * blockDim.x + threadIdx.x;
    if (i >= E4) return;
    int4 d = dst4[i];
    atomicAdd(&d_cnt[d.x], 1);
    atomicAdd(&d_cnt[d.y], 1);
    atomicAdd(&d_cnt[d.z], 1);
    atomicAdd(&d_cnt[d.w], 1);
}

__global__ void k_count_sc(const int* __restrict__ dst, int E) {
    int i = blockIdx.x * blockDim.x + threadIdx.x;
    if (i < E) atomicAdd(&d_cnt[dst[i]], 1);
}

// ---- prep: dinv, xd = x*dinv (pad 7->8), p init = xd -----------------------

__global__ void k_prep(const float* __restrict__ x, int n) {
    int i = blockIdx.x * blockDim.x + threadIdx.x;
    if (i >= n) return;
    float dv = rsqrtf((float)(d_cnt[i] + 1));   // +1 self loop
    d_dinv[i] = dv;
    const float* xi = x + (long long)i * 7;
    float4 a, b;
    a.x = xi[0] * dv; a.y = xi[1] * dv; a.z = xi[2] * dv; a.w = xi[3] * dv;
    b.x = xi[4] * dv; b.y = xi[5] * dv; b.z = xi[6] * dv; b.w = 0.0f;
    reinterpret_cast<float4*>(d_xd)[i * 2]     = a;
    reinterpret_cast<float4*>(d_xd)[i * 2 + 1] = b;
    reinterpret_cast<float4*>(d_p )[i * 2]     = a;
    reinterpret_cast<float4*>(d_p )[i * 2 + 1] = b;
}

// ---- layer-1 scatter: p[dst] += xd[src], fp32 (2 red.v4 / edge) ------------

__global__ void k_scatter8(const int* __restrict__ src,
                           const int* __restrict__ dst, int E) {
    long long idx = (long long)blockIdx.x * blockDim.x + threadIdx.x;
    int e = (int)(idx >> 1);
    int c = (int)(idx & 1);
    if (e >= E) return;
    int u = src[e], v = dst[e];
    float4 val = reinterpret_cast<const float4*>(d_xd)[(long long)u * 2 + c];
    red_add_v4f(&reinterpret_cast<float4*>(d_p)[(long long)v * 2 + c], val);
}

// ---- fused dense transform: 4 nodes per warp, LDS-amortized ----------------
// block = 256 threads = 8 warps = 32 nodes

__global__ void k_transform(const float* __restrict__ W1,
                            const float* __restrict__ b1,
                            const float* __restrict__ W2, int n) {
    __shared__ float W1s[7 * F1];
    __shared__ float b1s[F1];
    __shared__ float W2s[F1 * F2];
    __shared__ float hs[8][4][F1];     // [warp][node][feature], 8 KB

    for (int i = threadIdx.x; i < 7 * F1;  i += blockDim.x) W1s[i] = W1[i];
    for (int i = threadIdx.x; i < F1;      i += blockDim.x) b1s[i] = b1[i];
    for (int i = threadIdx.x; i < F1 * F2; i += blockDim.x) W2s[i] = W2[i];
    __syncthreads();

    int warp  = threadIdx.x >> 5;
    int lane  = threadIdx.x & 31;
    int base4 = blockIdx.x * 32 + warp * 4;   // first of this warp's 4 nodes
    if (base4 >= n) return;

    // one coalesced 128B load fetches p for all 4 nodes: lane = node*8 + feat
    int li = lane >> 3;                 // node slot 0..3
    int lf = lane & 7;                  // feature 0..7
    int node_ld = base4 + li; if (node_ld >= n) node_ld = n - 1;
    float pv  = d_p[node_ld * 8 + lf];
    float dvv = d_dinv[node_ld];

    // phase 1: h1 = relu(dinv*(p@W1)+b1) for the 4 nodes
    float dv[4];
    #pragma unroll
    for (int i = 0; i < 4; i++) {
        dv[i] = __shfl_sync(0xffffffffu, dvv, i * 8);
        float a0 = 0.0f, a1 = 0.0f;
        #pragma unroll
        for (int k = 0; k < 7; k++) {
            float pk = __shfl_sync(0xffffffffu, pv, i * 8 + k);
            a0 += pk * W1s[k * F1 + lane];
            a1 += pk * W1s[k * F1 + 32 + lane];
        }
        hs[warp][i][lane]      = fmaxf(dv[i] * a0 + b1s[lane],      0.0f);
        hs[warp][i][lane + 32] = fmaxf(dv[i] * a1 + b1s[lane + 32], 0.0f);
    }
    __syncwarp();

    // phase 2: g2 = (h1 @ W2) * dinv, k-loop step 4, float4 h-broadcasts
    float acc0 = 0.0f, acc1 = 0.0f, acc2 = 0.0f, acc3 = 0.0f;
    #pragma unroll
    for (int ks = 0; ks < F1; ks += 4) {
        float w0 = W2s[(ks    ) * F2 + lane];
        float w1 = W2s[(ks + 1) * F2 + lane];
        float w2 = W2s[(ks + 2) * F2 + lane];
        float w3 = W2s[(ks + 3) * F2 + lane];
        float4 h0 = *reinterpret_cast<const float4*>(&hs[warp][0][ks]);
        float4 h1 = *reinterpret_cast<const float4*>(&hs[warp][1][ks]);
        float4 h2 = *reinterpret_cast<const float4*>(&hs[warp][2][ks]);
        float4 h3 = *reinterpret_cast<const float4*>(&hs[warp][3][ks]);
        acc0 += h0.x * w0 + h0.y * w1 + h0.z * w2 + h0.w * w3;
        acc1 += h1.x * w0 + h1.y * w1 + h1.z * w2 + h1.w * w3;
        acc2 += h2.x * w0 + h2.y * w1 + h2.z * w2 + h2.w * w3;
        acc3 += h3.x * w0 + h3.y * w1 + h3.z * w2 + h3.w * w3;
    }

    float accs[4] = {acc0, acc1, acc2, acc3};
    #pragma unroll
    for (int i = 0; i < 4; i++) {
        int node = base4 + i;
        if (node < n) {
            __half g = __float2half(accs[i] * dv[i]);
            d_g2h[(node << 5) + lane] = g;
            d_s2h[(node << 5) + lane] = g;   // self-loop init
        }
    }
}

// ---- layer-2 scatter: s2h[dst] += g2h[src], fp16 (4 red.v4.f16x2 / edge) ---

__global__ void k_scatter32h(const int* __restrict__ src,
                             const int* __restrict__ dst, int E) {
    long long idx = (long long)blockIdx.x * blockDim.x + threadIdx.x;
    int e = (int)(idx >> 2);
    int c = (int)(idx & 3);
    if (e >= E) return;
    int u = src[e], v = dst[e];
    uint4 val = reinterpret_cast<const uint4*>(d_g2h)[(long long)u * 4 + c];
    red_add_v4h2(&reinterpret_cast<uint4*>(d_s2h)[(long long)v * 4 + c], val);
}

// ---- final: relu + classifier + log_softmax + cnt reset (thread/node) ------

__global__ void k_final(const float* __restrict__ b2,
                        const float* __restrict__ Wc,
                        const float* __restrict__ bc,
                        float* __restrict__ out, int n) {
    int node = blockIdx.x * blockDim.x + threadIdx.x;
    if (node >= n) return;

    float dv = d_dinv[node];
    const uint4* s4 = reinterpret_cast<const uint4*>(d_s2h) + (long long)node * 4;
    float l0 = bc[0], l1 = bc[1];

    #pragma unroll
    for (int j = 0; j < 4; j++) {
        uint4 q = s4[j];
        unsigned w[4] = {q.x, q.y, q.z, q.w};
        #pragma unroll
        for (int t = 0; t < 4; t++) {
            float2 v = __half22float2(*reinterpret_cast<const __half2*>(&w[t]));
            int k = j * 8 + t * 2;
            float h0 = fmaxf(dv * v.x + b2[k],     0.0f);
            float h1 = fmaxf(dv * v.y + b2[k + 1], 0.0f);
            l0 += h0 * Wc[k * 2]     + h1 * Wc[k * 2 + 2];
            l1 += h0 * Wc[k * 2 + 1] + h1 * Wc[k * 2 + 3];
        }
    }

    float m   = fmaxf(l0, l1);
    float lse = m + logf(expf(l0 - m) + expf(l1 - m));
    out[(long long)node * 2]     = l0 - lse;
    out[(long long)node * 2 + 1] = l1 - lse;
    d_cnt[node] = 0;   // reset histogram for next replay (deterministic)
}

// ---- launch ----------------------------------------------------------------

extern "C" void kernel_launch(void* const* d_in, const int* in_sizes, int n_in,
                              void* d_out, int out_size) {
    const float* x  = (const float*)d_in[0];
    const int*   ei = (const int*)  d_in[1];
    const float* W1 = (const float*)d_in[2];
    const float* b1 = (const float*)d_in[3];
    const float* W2 = (const float*)d_in[4];
    const float* b2 = (const float*)d_in[5];
    const float* Wc = (const float*)d_in[6];
    const float* bc = (const float*)d_in[7];
    float* out = (float*)d_out;

    int n = in_sizes[0] / 7;     // 100000
    int E = in_sizes[1] / 2;     // 1600000
    const int* src = ei;
    const int* dst = ei + E;

    const int T = 256;

    bool vec_ok = (E % 4 == 0) && ((((unsigned long long)dst) & 15ull) == 0);
    if (vec_ok) {
        int E4 = E / 4;
        k_count_v4<<<(E4 + T - 1) / T, T>>>((const int4*)dst, E4);
    } else {
        k_count_sc<<<(E + T - 1) / T, T>>>(dst, E);
    }

    k_prep<<<(n + T - 1) / T, T>>>(x, n);

    long long w1 = (long long)E * 2;
    k_scatter8<<<(unsigned)((w1 + T - 1) / T), T>>>(src, dst, E);

    k_transform<<<(n + 31) / 32, T>>>(W1, b1, W2, n);

    long long w2 = (long long)E * 4;
    k_scatter32h<<<(unsigned)((w2 + T - 1) / T), T>>>(src, dst, E);

    k_final<<<(n + T - 1) / T, T>>>(b2, Wc, bc, out, n);
}